// round 8
// baseline (speedup 1.0000x reference)
#include <cuda_runtime.h>
#include <cuda_bf16.h>
#include <cstdint>

#define NB   2048
#define NU   8192
#define ND   256
#define NR   8
#define KTOT (NR*ND + ND)   // 2304

// ---------------- scratch ----------------
__device__ __align__(16) __nv_bfloat16 g_Ah[(size_t)NB * KTOT];
__device__ __align__(16) __nv_bfloat16 g_Al[(size_t)NB * KTOT];
__device__ __align__(16) __nv_bfloat16 g_Bh[(size_t)ND * KTOT];   // B[n][k] = W[k][n]
__device__ __align__(16) __nv_bfloat16 g_Bl[(size_t)ND * KTOT];

#define GSPLIT 9
#define GKSPL  (KTOT / GSPLIT)   // 256 (== one relation per split; split 8 = self)
#define GCHUNK 32
#define GITERS (GKSPL / GCHUNK)  // 8
__device__ __align__(16) float g_part[(size_t)GSPLIT * NB * ND];

// work queue state (reset by build_w every replay)
__device__ int g_cursor;
__device__ int g_relcnt[9];

#define NSELF  512
#define PER_R  (2048 + 32)
#define NITEMS (NSELF + 8 * PER_R + 32)   // 17184

// ---------------- helpers ----------------
__device__ __forceinline__ uint32_t smem_u32(const void* p) {
    uint32_t a;
    asm("{ .reg .u64 t; cvta.to.shared.u64 t, %1; cvt.u32.u64 %0, t; }" : "=r"(a) : "l"(p));
    return a;
}
__device__ __forceinline__ void cp16(uint32_t dst, const void* src) {
    asm volatile("cp.async.ca.shared.global [%0], [%1], 16;" :: "r"(dst), "l"(src) : "memory");
}
__device__ __forceinline__ void cp_commit() { asm volatile("cp.async.commit_group;" ::: "memory"); }
__device__ __forceinline__ void cp_wait1()  { asm volatile("cp.async.wait_group 1;" ::: "memory"); }
__device__ __forceinline__ void cp_wait0()  { asm volatile("cp.async.wait_group 0;" ::: "memory"); }
__device__ __forceinline__ void ldm4(uint32_t* r, uint32_t addr) {
    asm volatile("ldmatrix.sync.aligned.m8n8.x4.shared.b16 {%0,%1,%2,%3}, [%4];"
        : "=r"(r[0]), "=r"(r[1]), "=r"(r[2]), "=r"(r[3]) : "r"(addr));
}
__device__ __forceinline__ void mma16816(float* d, const uint32_t* a, const uint32_t* b) {
    asm volatile("mma.sync.aligned.m16n8k16.row.col.f32.bf16.bf16.f32 "
        "{%0,%1,%2,%3}, {%4,%5,%6,%7}, {%8,%9}, {%0,%1,%2,%3};"
        : "+f"(d[0]), "+f"(d[1]), "+f"(d[2]), "+f"(d[3])
        : "r"(a[0]), "r"(a[1]), "r"(a[2]), "r"(a[3]), "r"(b[0]), "r"(b[1]));
}
__device__ __forceinline__ void bf16_split(float v, __nv_bfloat16& h, __nv_bfloat16& l) {
    h = __float2bfloat16(v);
    l = __float2bfloat16(v - __bfloat162float(h));
}

// ---------------- K1: build B = W^T (bf16 hi/lo) + reset queue state ----------------
__global__ void build_w_kernel(const float* __restrict__ weight,
                               const float* __restrict__ relw) {
    int n = blockIdx.x;
    int t = threadIdx.x;
    if (n == 0 && t < 16) {             // reset queue/counters for this replay
        if (t == 0) g_cursor = 0;
        if (t >= 1 && t <= 9) g_relcnt[t - 1] = 0;
    }
#pragma unroll
    for (int j = 0; j < 9; j++) {
        int k = j * 256 + t;
        float v;
        if (k < NR * ND) {
            int r = k >> 8, d = k & 255;
            v = relw[((size_t)r * ND + n) * ND + d];
        } else {
            v = weight[n * ND + (k - NR * ND)];
        }
        __nv_bfloat16 h, l;
        bf16_split(v, h, l);
        g_Bh[(size_t)n * KTOT + k] = h;
        g_Bl[(size_t)n * KTOT + k] = l;
    }
}

// ---------------- fused worker pieces ----------------

// self gather: item w covers batch rows w*4 .. w*4+3
__device__ void do_self(int w, int tid, const float* __restrict__ emb,
                        const int* __restrict__ nodes) {
    int b = w * 4 + (tid >> 6);
    int c = tid & 63;
    int src = nodes[b];
    float4 v = ((const float4*)emb)[(size_t)src * 64 + c];
    size_t base = (size_t)b * KTOT + NR * ND + c * 4;
    __nv_bfloat16 h, l;
    bf16_split(v.x, h, l); g_Ah[base + 0] = h; g_Al[base + 0] = l;
    bf16_split(v.y, h, l); g_Ah[base + 1] = h; g_Al[base + 1] = l;
    bf16_split(v.z, h, l); g_Ah[base + 2] = h; g_Al[base + 2] = l;
    bf16_split(v.w, h, l); g_Ah[base + 3] = h; g_Al[base + 3] = l;
    __threadfence();
    __syncthreads();
    if (tid == 0) atomicAdd(&g_relcnt[8], 1);
}

// mask scan (ballot) -> ordered index list -> MLP=4 gather
#define LIST_CAP 512
__device__ void do_mask(int rb, int tid, char* dsm,
                        const float* __restrict__ masks,
                        const float* __restrict__ emb,
                        const int* __restrict__ unique_idx) {
    uint32_t* s_bits = (uint32_t*)dsm;           // 1024 B
    uint16_t* s_list = (uint16_t*)(dsm + 1024);  // 1024 B
    int*      s_wtot = (int*)(dsm + 2048);       // 32 B
    int lane = tid & 31;
    int w = tid >> 5;
    int r = rb >> 11;
    int b = rb & 2047;

    const float4* row = (const float4*)(masks + (size_t)rb * NU);
#pragma unroll
    for (int c = 0; c < 8; c++) {
        float4 v = __ldcs(&row[c * 256 + tid]);
        uint32_t bx = __ballot_sync(0xffffffffu, v.x != 0.0f);
        uint32_t by = __ballot_sync(0xffffffffu, v.y != 0.0f);
        uint32_t bz = __ballot_sync(0xffffffffu, v.z != 0.0f);
        uint32_t bw = __ballot_sync(0xffffffffu, v.w != 0.0f);
        if (lane == 0) {
            int g = c * 8 + w;
            s_bits[g * 4 + 0] = bx;
            s_bits[g * 4 + 1] = by;
            s_bits[g * 4 + 2] = bz;
            s_bits[g * 4 + 3] = bw;
        }
    }
    __syncthreads();

    int Wd = w * 32 + lane;
    uint32_t bits = s_bits[Wd];
    int c = __popc(bits);
    int pre = c;
#pragma unroll
    for (int o = 1; o < 32; o <<= 1) {
        int v = __shfl_up_sync(0xffffffffu, pre, o);
        if (lane >= o) pre += v;
    }
    if (lane == 31) s_wtot[w] = pre;
    int excl = pre - c;
    __syncthreads();

    int base = 0, cnt = 0;
#pragma unroll
    for (int i = 0; i < 8; i++) {
        int v = s_wtot[i];
        if (i < w) base += v;
        cnt += v;
    }
    int pos = base + excl;
    {
        uint32_t bb = bits;
        int comp = Wd & 3;
        int g = Wd >> 2;
        int f4base = (g >> 3) * 256 + (g & 7) * 32;
        while (bb) {
            int j = __ffs(bb) - 1;
            bb &= bb - 1;
            if (pos < LIST_CAP) s_list[pos] = (uint16_t)((f4base + j) * 4 + comp);
            pos++;
        }
    }
    __syncthreads();

    int n = cnt < LIST_CAP ? cnt : LIST_CAP;
    float acc = 0.0f;
    int i = 0;
    for (; i + 4 <= n; i += 4) {
        int u0 = s_list[i], u1 = s_list[i + 1], u2 = s_list[i + 2], u3 = s_list[i + 3];
        int n0 = __ldg(&unique_idx[u0]);
        int n1 = __ldg(&unique_idx[u1]);
        int n2 = __ldg(&unique_idx[u2]);
        int n3 = __ldg(&unique_idx[u3]);
        float v0 = emb[(size_t)n0 * ND + tid];
        float v1 = emb[(size_t)n1 * ND + tid];
        float v2 = emb[(size_t)n2 * ND + tid];
        float v3 = emb[(size_t)n3 * ND + tid];
        acc = (((acc + v0) + v1) + v2) + v3;
    }
    for (; i < n; i++) acc += emb[(size_t)__ldg(&unique_idx[s_list[i]]) * ND + tid];

    float val = acc * (1.0f / ((float)cnt + 1e-10f));
    __nv_bfloat16 h, l;
    bf16_split(val, h, l);
    g_Ah[(size_t)b * KTOT + r * ND + tid] = h;
    g_Al[(size_t)b * KTOT + r * ND + tid] = l;
    __threadfence();
    __syncthreads();
    if (tid == 0) atomicAdd(&g_relcnt[r], 1);
}

// GEMM tile: 128x128, relation-split sp (K=256 slice)
#define SM_AH 0
#define SM_AL 10240
#define SM_BH 20480
#define SM_BL 30720
#define SM_BUF 40960
#define GSMEM (2 * SM_BUF)

__device__ __forceinline__ void load_chunk(uint32_t sbuf, int m0, int n0, int kc, int tid) {
#pragma unroll
    for (int p = 0; p < 4; p++) {
        int o = tid + p * 256;
        int src = o >> 9;
        int rem = o & 511;
        int row = rem >> 2;
        int c16 = rem & 3;
        const __nv_bfloat16* g = (src ? g_Al : g_Ah) + (size_t)(m0 + row) * KTOT + kc + c16 * 8;
        cp16(sbuf + (src ? SM_AL : SM_AH) + row * 80 + c16 * 16, g);
    }
#pragma unroll
    for (int p = 0; p < 4; p++) {
        int o = tid + p * 256;
        int src = o >> 9;
        int rem = o & 511;
        int row = rem >> 2;
        int c16 = rem & 3;
        const __nv_bfloat16* g = (src ? g_Bl : g_Bh) + (size_t)(n0 + row) * KTOT + kc + c16 * 8;
        cp16(sbuf + (src ? SM_BL : SM_BH) + row * 80 + c16 * 16, g);
    }
}

__device__ void do_gemm(int idx, int sp, int tid, char* smem,
                        const float*, const int*) {
    // wait for producer relation to complete
    if (tid == 0) {
        int target = (sp < 8) ? 2048 : NSELF;
        while (true) {
            int v;
            asm volatile("ld.acquire.gpu.b32 %0, [%1];" : "=r"(v)
                         : "l"(&g_relcnt[sp]) : "memory");
            if (v >= target) break;
            __nanosleep(128);
        }
    }
    __syncthreads();
    __threadfence();

    uint32_t sb = smem_u32(smem);
    int lane = tid & 31;
    int wid = tid >> 5;
    int wm = wid >> 2;
    int wn = wid & 3;
    int m0 = (idx >> 1) * 128;
    int n0 = (idx & 1) * 128;
    int kb = sp * GKSPL;

    float acc[4][4][4];
#pragma unroll
    for (int mi = 0; mi < 4; mi++)
#pragma unroll
        for (int nj = 0; nj < 4; nj++)
#pragma unroll
            for (int q = 0; q < 4; q++) acc[mi][nj][q] = 0.0f;

    load_chunk(sb, m0, n0, kb, tid);
    cp_commit();

    int lr = lane & 15;
    int lch = (lane >> 4) * 8;

    for (int it = 0; it < GITERS; it++) {
        uint32_t cbuf = sb + (it & 1) * SM_BUF;
        if (it + 1 < GITERS) {
            load_chunk(sb + ((it + 1) & 1) * SM_BUF, m0, n0, kb + (it + 1) * GCHUNK, tid);
            cp_commit();
            cp_wait1();
        } else {
            cp_wait0();
        }
        __syncthreads();

#pragma unroll
        for (int s = 0; s < 2; s++) {
            uint32_t ah[4][4], al[4][4], bh[4][2], bl[4][2];
#pragma unroll
            for (int mi = 0; mi < 4; mi++) {
                uint32_t off = (uint32_t)(wm * 64 + mi * 16 + lr) * 80 + (s * 16 + lch) * 2;
                ldm4(ah[mi], cbuf + SM_AH + off);
                ldm4(al[mi], cbuf + SM_AL + off);
            }
#pragma unroll
            for (int p = 0; p < 2; p++) {
                uint32_t off = (uint32_t)(wn * 32 + p * 16 + lr) * 80 + (s * 16 + lch) * 2;
                uint32_t r[4];
                ldm4(r, cbuf + SM_BH + off);
                bh[2 * p][0] = r[0]; bh[2 * p][1] = r[2];
                bh[2 * p + 1][0] = r[1]; bh[2 * p + 1][1] = r[3];
                ldm4(r, cbuf + SM_BL + off);
                bl[2 * p][0] = r[0]; bl[2 * p][1] = r[2];
                bl[2 * p + 1][0] = r[1]; bl[2 * p + 1][1] = r[3];
            }
#pragma unroll
            for (int mi = 0; mi < 4; mi++)
#pragma unroll
                for (int nj = 0; nj < 4; nj++)
                    mma16816(acc[mi][nj], ah[mi], bh[nj]);
#pragma unroll
            for (int mi = 0; mi < 4; mi++)
#pragma unroll
                for (int nj = 0; nj < 4; nj++)
                    mma16816(acc[mi][nj], ah[mi], bl[nj]);
#pragma unroll
            for (int mi = 0; mi < 4; mi++)
#pragma unroll
                for (int nj = 0; nj < 4; nj++)
                    mma16816(acc[mi][nj], al[mi], bh[nj]);
        }
        __syncthreads();
    }

    float* pB = g_part + (size_t)sp * NB * ND;
    int g = lane >> 2;
    int tq = lane & 3;
#pragma unroll
    for (int mi = 0; mi < 4; mi++) {
#pragma unroll
        for (int nj = 0; nj < 4; nj++) {
            int m = m0 + wm * 64 + mi * 16 + g;
            int n = n0 + wn * 32 + nj * 8 + tq * 2;
            float2 v0 = {acc[mi][nj][0], acc[mi][nj][1]};
            float2 v1 = {acc[mi][nj][2], acc[mi][nj][3]};
            *(float2*)&pB[(size_t)m * ND + n] = v0;
            *(float2*)&pB[(size_t)(m + 8) * ND + n] = v1;
        }
    }
}

// ---------------- K2: persistent fused worker ----------------
__global__ __launch_bounds__(256, 2) void fused_kernel(const float* __restrict__ masks,
                                                       const float* __restrict__ emb,
                                                       const int* __restrict__ unique_idx,
                                                       const int* __restrict__ nodes) {
    extern __shared__ char dsm[];
    __shared__ int s_item;
    int tid = threadIdx.x;

    while (true) {
        if (tid == 0) s_item = atomicAdd(&g_cursor, 1);
        __syncthreads();
        int w = s_item;
        __syncthreads();
        if (w >= NITEMS) break;

        if (w < NSELF) {
            do_self(w, tid, emb, nodes);
        } else {
            int x = w - NSELF;
            if (x < 8 * PER_R) {
                int r = x / PER_R;
                int y = x - r * PER_R;
                if (y < 2048) {
                    do_mask(r * 2048 + y, tid, dsm, masks, emb, unique_idx);
                } else {
                    do_gemm(y - 2048, r, tid, dsm, emb, unique_idx);
                }
            } else {
                do_gemm(x - 8 * PER_R, 8, tid, dsm, emb, unique_idx);
            }
        }
        __syncthreads();
    }
}

// ---------------- K3: deterministic reduce + ReLU ----------------
__global__ void reduce_relu_kernel(float* __restrict__ out) {
    int idx = blockIdx.x * 256 + threadIdx.x;
    const float4* p = (const float4*)g_part;
    float4 s = p[idx];
#pragma unroll
    for (int sp = 1; sp < GSPLIT; sp++) {
        float4 v = p[(size_t)sp * (NB * ND / 4) + idx];
        s.x += v.x; s.y += v.y; s.z += v.z; s.w += v.w;
    }
    s.x = s.x > 0.0f ? s.x : 0.0f;
    s.y = s.y > 0.0f ? s.y : 0.0f;
    s.z = s.z > 0.0f ? s.z : 0.0f;
    s.w = s.w > 0.0f ? s.w : 0.0f;
    ((float4*)out)[idx] = s;
}

// ---------------- launch ----------------
extern "C" void kernel_launch(void* const* d_in, const int* in_sizes, int n_in,
                              void* d_out, int out_size) {
    const int*   nodes  = nullptr;
    const int*   uniq   = nullptr;
    const float* masks  = nullptr;
    const float* emb    = nullptr;
    const float* weight = nullptr;
    const float* relw   = nullptr;

    for (int i = 0; i < n_in; i++) {
        switch (in_sizes[i]) {
            case NB:           nodes  = (const int*)d_in[i];   break;
            case NU:           uniq   = (const int*)d_in[i];   break;
            case NR * NB * NU: masks  = (const float*)d_in[i]; break;
            case 100000 * ND:  emb    = (const float*)d_in[i]; break;
            case ND * ND:      weight = (const float*)d_in[i]; break;
            case NR * ND * ND: relw   = (const float*)d_in[i]; break;
            default: break;
        }
    }
    float* out = (float*)d_out;

    static int smem_set = 0;
    if (!smem_set) {
        cudaFuncSetAttribute(fused_kernel, cudaFuncAttributeMaxDynamicSharedMemorySize, GSMEM);
        smem_set = 1;
    }

    build_w_kernel<<<ND, 256>>>(weight, relw);
    fused_kernel<<<296, 256, GSMEM>>>(masks, emb, uniq, nodes);
    reduce_relu_kernel<<<NB * ND / 4 / 256, 256>>>(out);
}

// round 9
// speedup vs baseline: 1.1977x; 1.1977x over previous
#include <cuda_runtime.h>
#include <cuda_bf16.h>
#include <cstdint>

#define NB   2048
#define NU   8192
#define ND   256
#define NR   8
#define KTOT (NR*ND + ND)   // 2304

// ---------------- scratch ----------------
__device__ __align__(16) __nv_bfloat16 g_Ah[(size_t)NB * KTOT];
__device__ __align__(16) __nv_bfloat16 g_Al[(size_t)NB * KTOT];
__device__ __align__(16) __nv_bfloat16 g_Bh[(size_t)ND * KTOT];   // B[n][k] = W[k][n]
__device__ __align__(16) __nv_bfloat16 g_Bl[(size_t)ND * KTOT];

#define GSPLIT 9
#define GKSPL  (KTOT / GSPLIT)   // 256 (one relation per split; split 8 = self)
#define GCHUNK 32
#define GITERS (GKSPL / GCHUNK)  // 8
__device__ __align__(16) float g_part[(size_t)GSPLIT * NB * ND];

// ---------------- helpers ----------------
__device__ __forceinline__ uint32_t smem_u32(const void* p) {
    uint32_t a;
    asm("{ .reg .u64 t; cvta.to.shared.u64 t, %1; cvt.u32.u64 %0, t; }" : "=r"(a) : "l"(p));
    return a;
}
__device__ __forceinline__ void cp16(uint32_t dst, const void* src) {
    asm volatile("cp.async.ca.shared.global [%0], [%1], 16;" :: "r"(dst), "l"(src) : "memory");
}
__device__ __forceinline__ void cp_commit() { asm volatile("cp.async.commit_group;" ::: "memory"); }
__device__ __forceinline__ void cp_wait1()  { asm volatile("cp.async.wait_group 1;" ::: "memory"); }
__device__ __forceinline__ void cp_wait0()  { asm volatile("cp.async.wait_group 0;" ::: "memory"); }
__device__ __forceinline__ void ldm4(uint32_t* r, uint32_t addr) {
    asm volatile("ldmatrix.sync.aligned.m8n8.x4.shared.b16 {%0,%1,%2,%3}, [%4];"
        : "=r"(r[0]), "=r"(r[1]), "=r"(r[2]), "=r"(r[3]) : "r"(addr));
}
__device__ __forceinline__ void mma16816(float* d, const uint32_t* a, const uint32_t* b) {
    asm volatile("mma.sync.aligned.m16n8k16.row.col.f32.bf16.bf16.f32 "
        "{%0,%1,%2,%3}, {%4,%5,%6,%7}, {%8,%9}, {%0,%1,%2,%3};"
        : "+f"(d[0]), "+f"(d[1]), "+f"(d[2]), "+f"(d[3])
        : "r"(a[0]), "r"(a[1]), "r"(a[2]), "r"(a[3]), "r"(b[0]), "r"(b[1]));
}
__device__ __forceinline__ void bf16_split(float v, __nv_bfloat16& h, __nv_bfloat16& l) {
    h = __float2bfloat16(v);
    l = __float2bfloat16(v - __bfloat162float(h));
}

// ---------------- K1a: build B = W^T (bf16 hi/lo) ----------------
__global__ void build_w_kernel(const float* __restrict__ weight,
                               const float* __restrict__ relw) {
    int n = blockIdx.x;
    int t = threadIdx.x;
#pragma unroll
    for (int j = 0; j < 9; j++) {
        int k = j * 256 + t;
        float v;
        if (k < NR * ND) {
            int r = k >> 8, d = k & 255;
            v = relw[((size_t)r * ND + n) * ND + d];
        } else {
            v = weight[n * ND + (k - NR * ND)];
        }
        __nv_bfloat16 h, l;
        bf16_split(v, h, l);
        g_Bh[(size_t)n * KTOT + k] = h;
        g_Bl[(size_t)n * KTOT + k] = l;
    }
}

// ---------------- K1b: self-row gather ----------------
__global__ void gather_self_kernel(const float* __restrict__ emb,
                                   const int* __restrict__ nodes) {
    int blk = blockIdx.x;
    int t = threadIdx.x;
    int b = blk * 4 + (t >> 6);
    int c = t & 63;
    int src = nodes[b];
    float4 v = ((const float4*)emb)[(size_t)src * 64 + c];
    size_t base = (size_t)b * KTOT + NR * ND + c * 4;
    __nv_bfloat16 h, l;
    bf16_split(v.x, h, l); g_Ah[base + 0] = h; g_Al[base + 0] = l;
    bf16_split(v.y, h, l); g_Ah[base + 1] = h; g_Al[base + 1] = l;
    bf16_split(v.z, h, l); g_Ah[base + 2] = h; g_Al[base + 2] = l;
    bf16_split(v.w, h, l); g_Ah[base + 3] = h; g_Al[base + 3] = l;
}

// ---------------- K2: per-relation mask scan + aggregation ----------------
// One block per b (grid 2048, relation passed in). Prefetch all 8 float4
// (MLP=8) before ballots; cooperative bitmap->list decode; MLP=4 gather.
#define LIST_CAP 512
__global__ void mask_agg_kernel(int r,
                                const float* __restrict__ masks,
                                const float* __restrict__ emb,
                                const int* __restrict__ unique_idx) {
    __shared__ uint32_t s_bits[256];
    __shared__ uint16_t s_list[LIST_CAP];
    __shared__ int s_wtot[8];
    int t = threadIdx.x;
    int lane = t & 31;
    int w = t >> 5;
    int b = blockIdx.x;
    int rb = r * 2048 + b;

    const float4* row = (const float4*)(masks + (size_t)rb * NU);
    float4 v[8];
#pragma unroll
    for (int c = 0; c < 8; c++) v[c] = __ldcs(&row[c * 256 + t]);   // 8 loads in flight

#pragma unroll
    for (int c = 0; c < 8; c++) {
        uint32_t bx = __ballot_sync(0xffffffffu, v[c].x != 0.0f);
        uint32_t by = __ballot_sync(0xffffffffu, v[c].y != 0.0f);
        uint32_t bz = __ballot_sync(0xffffffffu, v[c].z != 0.0f);
        uint32_t bw = __ballot_sync(0xffffffffu, v[c].w != 0.0f);
        if (lane == 0) {
            int g = c * 8 + w;
            s_bits[g * 4 + 0] = bx;
            s_bits[g * 4 + 1] = by;
            s_bits[g * 4 + 2] = bz;
            s_bits[g * 4 + 3] = bw;
        }
    }
    __syncthreads();

    int Wd = w * 32 + lane;
    uint32_t bits = s_bits[Wd];
    int c = __popc(bits);
    int pre = c;
#pragma unroll
    for (int o = 1; o < 32; o <<= 1) {
        int x = __shfl_up_sync(0xffffffffu, pre, o);
        if (lane >= o) pre += x;
    }
    if (lane == 31) s_wtot[w] = pre;
    int excl = pre - c;
    __syncthreads();

    int base = 0, cnt = 0;
#pragma unroll
    for (int i = 0; i < 8; i++) {
        int x = s_wtot[i];
        if (i < w) base += x;
        cnt += x;
    }
    int pos = base + excl;
    {
        uint32_t bb = bits;
        int comp = Wd & 3;
        int g = Wd >> 2;
        int f4base = (g >> 3) * 256 + (g & 7) * 32;
        while (bb) {
            int j = __ffs(bb) - 1;
            bb &= bb - 1;
            if (pos < LIST_CAP) s_list[pos] = (uint16_t)((f4base + j) * 4 + comp);
            pos++;
        }
    }
    __syncthreads();

    int n = cnt < LIST_CAP ? cnt : LIST_CAP;
    float acc = 0.0f;
    int i = 0;
    for (; i + 4 <= n; i += 4) {
        int u0 = s_list[i], u1 = s_list[i + 1], u2 = s_list[i + 2], u3 = s_list[i + 3];
        int n0 = __ldg(&unique_idx[u0]);
        int n1 = __ldg(&unique_idx[u1]);
        int n2 = __ldg(&unique_idx[u2]);
        int n3 = __ldg(&unique_idx[u3]);
        float v0 = emb[(size_t)n0 * ND + t];
        float v1 = emb[(size_t)n1 * ND + t];
        float v2 = emb[(size_t)n2 * ND + t];
        float v3 = emb[(size_t)n3 * ND + t];
        acc = (((acc + v0) + v1) + v2) + v3;
    }
    for (; i < n; i++) acc += emb[(size_t)__ldg(&unique_idx[s_list[i]]) * ND + t];

    float val = acc * (1.0f / ((float)cnt + 1e-10f));
    __nv_bfloat16 h, l;
    bf16_split(val, h, l);
    g_Ah[(size_t)b * KTOT + r * ND + t] = h;
    g_Al[(size_t)b * KTOT + r * ND + t] = l;
}

// ---------------- K3: per-split mma.sync bf16 GEMM (grid 16x2) ----------------
#define SM_AH 0
#define SM_AL 10240
#define SM_BH 20480
#define SM_BL 30720
#define SM_BUF 40960
#define GSMEM (2 * SM_BUF)

__device__ __forceinline__ void load_chunk(uint32_t sbuf, int m0, int n0, int kc, int tid) {
#pragma unroll
    for (int p = 0; p < 4; p++) {
        int o = tid + p * 256;
        int src = o >> 9;
        int rem = o & 511;
        int row = rem >> 2;
        int c16 = rem & 3;
        const __nv_bfloat16* g = (src ? g_Al : g_Ah) + (size_t)(m0 + row) * KTOT + kc + c16 * 8;
        cp16(sbuf + (src ? SM_AL : SM_AH) + row * 80 + c16 * 16, g);
    }
#pragma unroll
    for (int p = 0; p < 4; p++) {
        int o = tid + p * 256;
        int src = o >> 9;
        int rem = o & 511;
        int row = rem >> 2;
        int c16 = rem & 3;
        const __nv_bfloat16* g = (src ? g_Bl : g_Bh) + (size_t)(n0 + row) * KTOT + kc + c16 * 8;
        cp16(sbuf + (src ? SM_BL : SM_BH) + row * 80 + c16 * 16, g);
    }
}

__global__ __launch_bounds__(256, 2) void gemm_mma_kernel(int sp) {
    extern __shared__ char smem[];
    uint32_t sb = smem_u32(smem);
    int tid = threadIdx.x;
    int lane = tid & 31;
    int wid = tid >> 5;
    int wm = wid >> 2;
    int wn = wid & 3;
    int m0 = blockIdx.x * 128;
    int n0 = blockIdx.y * 128;
    int kb = sp * GKSPL;

    float acc[4][4][4];
#pragma unroll
    for (int mi = 0; mi < 4; mi++)
#pragma unroll
        for (int nj = 0; nj < 4; nj++)
#pragma unroll
            for (int q = 0; q < 4; q++) acc[mi][nj][q] = 0.0f;

    load_chunk(sb, m0, n0, kb, tid);
    cp_commit();

    int lr = lane & 15;
    int lch = (lane >> 4) * 8;

    for (int it = 0; it < GITERS; it++) {
        uint32_t cbuf = sb + (it & 1) * SM_BUF;
        if (it + 1 < GITERS) {
            load_chunk(sb + ((it + 1) & 1) * SM_BUF, m0, n0, kb + (it + 1) * GCHUNK, tid);
            cp_commit();
            cp_wait1();
        } else {
            cp_wait0();
        }
        __syncthreads();

#pragma unroll
        for (int s = 0; s < 2; s++) {
            uint32_t ah[4][4], al[4][4], bh[4][2], bl[4][2];
#pragma unroll
            for (int mi = 0; mi < 4; mi++) {
                uint32_t off = (uint32_t)(wm * 64 + mi * 16 + lr) * 80 + (s * 16 + lch) * 2;
                ldm4(ah[mi], cbuf + SM_AH + off);
                ldm4(al[mi], cbuf + SM_AL + off);
            }
#pragma unroll
            for (int p = 0; p < 2; p++) {
                uint32_t off = (uint32_t)(wn * 32 + p * 16 + lr) * 80 + (s * 16 + lch) * 2;
                uint32_t r[4];
                ldm4(r, cbuf + SM_BH + off);
                bh[2 * p][0] = r[0]; bh[2 * p][1] = r[2];
                bh[2 * p + 1][0] = r[1]; bh[2 * p + 1][1] = r[3];
                ldm4(r, cbuf + SM_BL + off);
                bl[2 * p][0] = r[0]; bl[2 * p][1] = r[2];
                bl[2 * p + 1][0] = r[1]; bl[2 * p + 1][1] = r[3];
            }
#pragma unroll
            for (int mi = 0; mi < 4; mi++)
#pragma unroll
                for (int nj = 0; nj < 4; nj++)
                    mma16816(acc[mi][nj], ah[mi], bh[nj]);
#pragma unroll
            for (int mi = 0; mi < 4; mi++)
#pragma unroll
                for (int nj = 0; nj < 4; nj++)
                    mma16816(acc[mi][nj], ah[mi], bl[nj]);
#pragma unroll
            for (int mi = 0; mi < 4; mi++)
#pragma unroll
                for (int nj = 0; nj < 4; nj++)
                    mma16816(acc[mi][nj], al[mi], bh[nj]);
        }
        __syncthreads();
    }

    float* pB = g_part + (size_t)sp * NB * ND;
    int g = lane >> 2;
    int tq = lane & 3;
#pragma unroll
    for (int mi = 0; mi < 4; mi++) {
#pragma unroll
        for (int nj = 0; nj < 4; nj++) {
            int m = m0 + wm * 64 + mi * 16 + g;
            int n = n0 + wn * 32 + nj * 8 + tq * 2;
            float2 v0 = {acc[mi][nj][0], acc[mi][nj][1]};
            float2 v1 = {acc[mi][nj][2], acc[mi][nj][3]};
            *(float2*)&pB[(size_t)m * ND + n] = v0;
            *(float2*)&pB[(size_t)(m + 8) * ND + n] = v1;
        }
    }
}

// ---------------- K4: deterministic reduce + ReLU ----------------
__global__ void reduce_relu_kernel(float* __restrict__ out) {
    int idx = blockIdx.x * 256 + threadIdx.x;
    const float4* p = (const float4*)g_part;
    float4 s = p[idx];
#pragma unroll
    for (int sp = 1; sp < GSPLIT; sp++) {
        float4 v = p[(size_t)sp * (NB * ND / 4) + idx];
        s.x += v.x; s.y += v.y; s.z += v.z; s.w += v.w;
    }
    s.x = s.x > 0.0f ? s.x : 0.0f;
    s.y = s.y > 0.0f ? s.y : 0.0f;
    s.z = s.z > 0.0f ? s.z : 0.0f;
    s.w = s.w > 0.0f ? s.w : 0.0f;
    ((float4*)out)[idx] = s;
}

// ---------------- launch: two-branch graph via event fork ----------------
extern "C" void kernel_launch(void* const* d_in, const int* in_sizes, int n_in,
                              void* d_out, int out_size) {
    const int*   nodes  = nullptr;
    const int*   uniq   = nullptr;
    const float* masks  = nullptr;
    const float* emb    = nullptr;
    const float* weight = nullptr;
    const float* relw   = nullptr;

    for (int i = 0; i < n_in; i++) {
        switch (in_sizes[i]) {
            case NB:           nodes  = (const int*)d_in[i];   break;
            case NU:           uniq   = (const int*)d_in[i];   break;
            case NR * NB * NU: masks  = (const float*)d_in[i]; break;
            case 100000 * ND:  emb    = (const float*)d_in[i]; break;
            case ND * ND:      weight = (const float*)d_in[i]; break;
            case NR * ND * ND: relw   = (const float*)d_in[i]; break;
            default: break;
        }
    }
    float* out = (float*)d_out;

    static int inited = 0;
    static cudaStream_t s2;
    static cudaEvent_t evSelf, evR[NR], evJoin;
    if (!inited) {
        cudaFuncSetAttribute(gemm_mma_kernel, cudaFuncAttributeMaxDynamicSharedMemorySize, GSMEM);
        cudaStreamCreateWithFlags(&s2, cudaStreamNonBlocking);
        cudaEventCreateWithFlags(&evSelf, cudaEventDisableTiming);
        for (int r = 0; r < NR; r++) cudaEventCreateWithFlags(&evR[r], cudaEventDisableTiming);
        cudaEventCreateWithFlags(&evJoin, cudaEventDisableTiming);
        inited = 1;
    }

    // main branch (stream 0): weights, self gather, 8 mask kernels
    build_w_kernel<<<ND, 256>>>(weight, relw);
    gather_self_kernel<<<NB / 4, 256>>>(emb, nodes);
    cudaEventRecord(evSelf, 0);
    cudaStreamWaitEvent(s2, evSelf, 0);        // fork: s2 joins capture here
    gemm_mma_kernel<<<dim3(16, 2), 256, GSMEM, s2>>>(8);   // self split

    for (int r = 0; r < NR; r++) {
        mask_agg_kernel<<<NB, 256>>>(r, masks, emb, uniq);
        cudaEventRecord(evR[r], 0);
        cudaStreamWaitEvent(s2, evR[r], 0);
        gemm_mma_kernel<<<dim3(16, 2), 256, GSMEM, s2>>>(r);
    }

    cudaEventRecord(evJoin, s2);               // rejoin before capture ends
    cudaStreamWaitEvent(0, evJoin, 0);
    reduce_relu_kernel<<<NB * ND / 4 / 256, 256>>>(out);
}

// round 10
// speedup vs baseline: 2.4628x; 2.0563x over previous
#include <cuda_runtime.h>
#include <cuda_fp16.h>
#include <cstdint>

#define NB   2048
#define NU   8192
#define ND   256
#define NR   8
#define KTOT (NR*ND + ND)   // 2304

// ---------------- scratch ----------------
__device__ __align__(16) __half g_Ah[(size_t)NB * KTOT];   // 9.4 MB
__device__ __align__(16) __half g_Bh[(size_t)ND * KTOT];   // B[n][k] = W[k][n]

#define GSPLIT 9
#define GKSPL  (KTOT / GSPLIT)   // 256
#define GCHUNK 32
#define GITERS (GKSPL / GCHUNK)  // 8
__device__ __align__(16) float g_part[(size_t)GSPLIT * NB * ND];

// ---------------- helpers ----------------
__device__ __forceinline__ uint32_t smem_u32(const void* p) {
    uint32_t a;
    asm("{ .reg .u64 t; cvta.to.shared.u64 t, %1; cvt.u32.u64 %0, t; }" : "=r"(a) : "l"(p));
    return a;
}
__device__ __forceinline__ void cp16(uint32_t dst, const void* src) {
    asm volatile("cp.async.ca.shared.global [%0], [%1], 16;" :: "r"(dst), "l"(src) : "memory");
}
__device__ __forceinline__ void cp_commit() { asm volatile("cp.async.commit_group;" ::: "memory"); }
__device__ __forceinline__ void cp_wait1()  { asm volatile("cp.async.wait_group 1;" ::: "memory"); }
__device__ __forceinline__ void cp_wait0()  { asm volatile("cp.async.wait_group 0;" ::: "memory"); }
__device__ __forceinline__ void ldm4(uint32_t* r, uint32_t addr) {
    asm volatile("ldmatrix.sync.aligned.m8n8.x4.shared.b16 {%0,%1,%2,%3}, [%4];"
        : "=r"(r[0]), "=r"(r[1]), "=r"(r[2]), "=r"(r[3]) : "r"(addr));
}
__device__ __forceinline__ void mma16816(float* d, const uint32_t* a, const uint32_t* b) {
    asm volatile("mma.sync.aligned.m16n8k16.row.col.f32.f16.f16.f32 "
        "{%0,%1,%2,%3}, {%4,%5,%6,%7}, {%8,%9}, {%0,%1,%2,%3};"
        : "+f"(d[0]), "+f"(d[1]), "+f"(d[2]), "+f"(d[3])
        : "r"(a[0]), "r"(a[1]), "r"(a[2]), "r"(a[3]), "r"(b[0]), "r"(b[1]));
}

// ---------------- K1a: build B = W^T (fp16) ----------------
__global__ void build_w_kernel(const float* __restrict__ weight,
                               const float* __restrict__ relw) {
    int n = blockIdx.x;
    int j = blockIdx.y;
    int t = threadIdx.x;
    int k = j * 256 + t;
    float v;
    if (k < NR * ND) {
        int r = k >> 8, d = k & 255;
        v = relw[((size_t)r * ND + n) * ND + d];
    } else {
        v = weight[n * ND + (k - NR * ND)];
    }
    g_Bh[(size_t)n * KTOT + k] = __float2half_rn(v);
}

// ---------------- K1b: self-row gather ----------------
__global__ void gather_self_kernel(const float* __restrict__ emb,
                                   const int* __restrict__ nodes) {
    int blk = blockIdx.x;
    int t = threadIdx.x;
    int b = blk * 4 + (t >> 6);
    int c = t & 63;
    int src = nodes[b];
    float4 v = ((const float4*)emb)[(size_t)src * 64 + c];
    size_t base = (size_t)b * KTOT + NR * ND + c * 4;
    __half2* dst = (__half2*)&g_Ah[base];
    dst[0] = __floats2half2_rn(v.x, v.y);
    dst[1] = __floats2half2_rn(v.z, v.w);
}

// ---------------- K2: mask scan (ballot) -> index list -> MLP=4 gather ----------------
#define LIST_CAP 512
__global__ void mask_agg_kernel(const float* __restrict__ masks,
                                const float* __restrict__ emb,
                                const int* __restrict__ unique_idx) {
    __shared__ uint32_t s_bits[256];
    __shared__ uint16_t s_list[LIST_CAP];
    __shared__ int s_wtot[8];
    int t = threadIdx.x;
    int lane = t & 31;
    int w = t >> 5;
    int rb = blockIdx.x;
    int r = rb >> 11;
    int b = rb & 2047;

    const float4* row = (const float4*)(masks + (size_t)rb * NU);
    float4 v[8];
#pragma unroll
    for (int c = 0; c < 8; c++) v[c] = __ldcs(&row[c * 256 + t]);   // MLP=8

#pragma unroll
    for (int c = 0; c < 8; c++) {
        uint32_t bx = __ballot_sync(0xffffffffu, v[c].x != 0.0f);
        uint32_t by = __ballot_sync(0xffffffffu, v[c].y != 0.0f);
        uint32_t bz = __ballot_sync(0xffffffffu, v[c].z != 0.0f);
        uint32_t bw = __ballot_sync(0xffffffffu, v[c].w != 0.0f);
        if (lane == 0) {
            int g = c * 8 + w;
            s_bits[g * 4 + 0] = bx;
            s_bits[g * 4 + 1] = by;
            s_bits[g * 4 + 2] = bz;
            s_bits[g * 4 + 3] = bw;
        }
    }
    __syncthreads();

    int Wd = w * 32 + lane;
    uint32_t bits = s_bits[Wd];
    int c = __popc(bits);
    int pre = c;
#pragma unroll
    for (int o = 1; o < 32; o <<= 1) {
        int x = __shfl_up_sync(0xffffffffu, pre, o);
        if (lane >= o) pre += x;
    }
    if (lane == 31) s_wtot[w] = pre;
    int excl = pre - c;
    __syncthreads();

    int base = 0, cnt = 0;
#pragma unroll
    for (int i = 0; i < 8; i++) {
        int x = s_wtot[i];
        if (i < w) base += x;
        cnt += x;
    }
    int pos = base + excl;
    {
        uint32_t bb = bits;
        int comp = Wd & 3;
        int g = Wd >> 2;
        int f4base = (g >> 3) * 256 + (g & 7) * 32;
        while (bb) {
            int j = __ffs(bb) - 1;
            bb &= bb - 1;
            if (pos < LIST_CAP) s_list[pos] = (uint16_t)((f4base + j) * 4 + comp);
            pos++;
        }
    }
    __syncthreads();

    int n = cnt < LIST_CAP ? cnt : LIST_CAP;
    float acc = 0.0f;
    int i = 0;
    for (; i + 4 <= n; i += 4) {
        int u0 = s_list[i], u1 = s_list[i + 1], u2 = s_list[i + 2], u3 = s_list[i + 3];
        int n0 = __ldg(&unique_idx[u0]);
        int n1 = __ldg(&unique_idx[u1]);
        int n2 = __ldg(&unique_idx[u2]);
        int n3 = __ldg(&unique_idx[u3]);
        float v0 = emb[(size_t)n0 * ND + t];
        float v1 = emb[(size_t)n1 * ND + t];
        float v2 = emb[(size_t)n2 * ND + t];
        float v3 = emb[(size_t)n3 * ND + t];
        acc = (((acc + v0) + v1) + v2) + v3;
    }
    for (; i < n; i++) acc += emb[(size_t)__ldg(&unique_idx[s_list[i]]) * ND + t];

    float val = acc * (1.0f / ((float)cnt + 1e-10f));
    g_Ah[(size_t)b * KTOT + r * ND + t] = __float2half_rn(val);
}

// ---------------- K3: mma.sync fp16 GEMM ----------------
// Block 128x128, 8 warps (2m x 4n), k-chunk 32, cp.async double-buffered.
// grid (16, 2, GSPLIT) = 288 blocks. SMEM: A 10240 + B 10240 per buffer.
#define SM_AH 0
#define SM_BH 10240
#define SM_BUF 20480
#define GSMEM (2 * SM_BUF)

__device__ __forceinline__ void load_chunk(uint32_t sbuf, int m0, int n0, int kc, int tid) {
#pragma unroll
    for (int p = 0; p < 2; p++) {
        int o = tid + p * 256;
        int row = o >> 2;
        int c16 = o & 3;
        const __half* g = g_Ah + (size_t)(m0 + row) * KTOT + kc + c16 * 8;
        cp16(sbuf + SM_AH + row * 80 + c16 * 16, g);
    }
#pragma unroll
    for (int p = 0; p < 2; p++) {
        int o = tid + p * 256;
        int row = o >> 2;
        int c16 = o & 3;
        const __half* g = g_Bh + (size_t)(n0 + row) * KTOT + kc + c16 * 8;
        cp16(sbuf + SM_BH + row * 80 + c16 * 16, g);
    }
}

__global__ __launch_bounds__(256, 2) void gemm_mma_kernel() {
    extern __shared__ char smem[];
    uint32_t sb = smem_u32(smem);
    int tid = threadIdx.x;
    int lane = tid & 31;
    int wid = tid >> 5;
    int wm = wid >> 2;
    int wn = wid & 3;
    int m0 = blockIdx.x * 128;
    int n0 = blockIdx.y * 128;
    int sp = blockIdx.z;
    int kb = sp * GKSPL;

    float acc[4][4][4];
#pragma unroll
    for (int mi = 0; mi < 4; mi++)
#pragma unroll
        for (int nj = 0; nj < 4; nj++)
#pragma unroll
            for (int q = 0; q < 4; q++) acc[mi][nj][q] = 0.0f;

    load_chunk(sb, m0, n0, kb, tid);
    cp_commit();

    int lr = lane & 15;
    int lch = (lane >> 4) * 8;

    for (int it = 0; it < GITERS; it++) {
        uint32_t cbuf = sb + (it & 1) * SM_BUF;
        if (it + 1 < GITERS) {
            load_chunk(sb + ((it + 1) & 1) * SM_BUF, m0, n0, kb + (it + 1) * GCHUNK, tid);
            cp_commit();
            cp_wait1();
        } else {
            cp_wait0();
        }
        __syncthreads();

#pragma unroll
        for (int s = 0; s < 2; s++) {
            uint32_t ah[4][4], bh[4][2];
#pragma unroll
            for (int mi = 0; mi < 4; mi++) {
                uint32_t off = (uint32_t)(wm * 64 + mi * 16 + lr) * 80 + (s * 16 + lch) * 2;
                ldm4(ah[mi], cbuf + SM_AH + off);
            }
#pragma unroll
            for (int p = 0; p < 2; p++) {
                uint32_t off = (uint32_t)(wn * 32 + p * 16 + lr) * 80 + (s * 16 + lch) * 2;
                uint32_t r[4];
                ldm4(r, cbuf + SM_BH + off);
                bh[2 * p][0] = r[0]; bh[2 * p][1] = r[2];
                bh[2 * p + 1][0] = r[1]; bh[2 * p + 1][1] = r[3];
            }
#pragma unroll
            for (int mi = 0; mi < 4; mi++)
#pragma unroll
                for (int nj = 0; nj < 4; nj++)
                    mma16816(acc[mi][nj], ah[mi], bh[nj]);
        }
        __syncthreads();
    }

    float* pB = g_part + (size_t)sp * NB * ND;
    int g = lane >> 2;
    int tq = lane & 3;
#pragma unroll
    for (int mi = 0; mi < 4; mi++) {
#pragma unroll
        for (int nj = 0; nj < 4; nj++) {
            int m = m0 + wm * 64 + mi * 16 + g;
            int n = n0 + wn * 32 + nj * 8 + tq * 2;
            float2 v0 = {acc[mi][nj][0], acc[mi][nj][1]};
            float2 v1 = {acc[mi][nj][2], acc[mi][nj][3]};
            *(float2*)&pB[(size_t)m * ND + n] = v0;
            *(float2*)&pB[(size_t)(m + 8) * ND + n] = v1;
        }
    }
}

// ---------------- K4: deterministic reduce + ReLU ----------------
__global__ void reduce_relu_kernel(float* __restrict__ out) {
    int idx = blockIdx.x * 256 + threadIdx.x;
    const float4* p = (const float4*)g_part;
    float4 s = p[idx];
#pragma unroll
    for (int sp = 1; sp < GSPLIT; sp++) {
        float4 v = p[(size_t)sp * (NB * ND / 4) + idx];
        s.x += v.x; s.y += v.y; s.z += v.z; s.w += v.w;
    }
    s.x = s.x > 0.0f ? s.x : 0.0f;
    s.y = s.y > 0.0f ? s.y : 0.0f;
    s.z = s.z > 0.0f ? s.z : 0.0f;
    s.w = s.w > 0.0f ? s.w : 0.0f;
    ((float4*)out)[idx] = s;
}

// ---------------- launch (serial, single stream) ----------------
extern "C" void kernel_launch(void* const* d_in, const int* in_sizes, int n_in,
                              void* d_out, int out_size) {
    const int*   nodes  = nullptr;
    const int*   uniq   = nullptr;
    const float* masks  = nullptr;
    const float* emb    = nullptr;
    const float* weight = nullptr;
    const float* relw   = nullptr;

    for (int i = 0; i < n_in; i++) {
        switch (in_sizes[i]) {
            case NB:           nodes  = (const int*)d_in[i];   break;
            case NU:           uniq   = (const int*)d_in[i];   break;
            case NR * NB * NU: masks  = (const float*)d_in[i]; break;
            case 100000 * ND:  emb    = (const float*)d_in[i]; break;
            case ND * ND:      weight = (const float*)d_in[i]; break;
            case NR * ND * ND: relw   = (const float*)d_in[i]; break;
            default: break;
        }
    }
    float* out = (float*)d_out;

    static int smem_set = 0;
    if (!smem_set) {
        cudaFuncSetAttribute(gemm_mma_kernel, cudaFuncAttributeMaxDynamicSharedMemorySize, GSMEM);
        smem_set = 1;
    }

    build_w_kernel<<<dim3(ND, 9), 256>>>(weight, relw);
    gather_self_kernel<<<NB / 4, 256>>>(emb, nodes);
    mask_agg_kernel<<<NR * NB, 256>>>(masks, emb, uniq);
    dim3 g3(NB / 128, ND / 128, GSPLIT);
    gemm_mma_kernel<<<g3, 256, GSMEM>>>();
    reduce_relu_kernel<<<NB * ND / 4 / 256, 256>>>(out);
}

// round 11
// speedup vs baseline: 2.5337x; 1.0288x over previous
#include <cuda_runtime.h>
#include <cuda_fp16.h>
#include <cstdint>

#define NB   2048
#define NU   8192
#define ND   256
#define NR   8
#define KTOT (NR*ND + ND)   // 2304

// ---------------- scratch ----------------
__device__ __align__(16) __half g_Ah[(size_t)NB * KTOT];   // 9.4 MB
__device__ __align__(16) __half g_Bh[(size_t)ND * KTOT];   // B[n][k] = W[k][n]

#define GSPLIT 9
#define GKSPL  (KTOT / GSPLIT)   // 256
#define GCHUNK 32
#define GITERS (GKSPL / GCHUNK)  // 8
__device__ __align__(16) float g_part[(size_t)GSPLIT * NB * ND];

// ---------------- helpers ----------------
__device__ __forceinline__ uint32_t smem_u32(const void* p) {
    uint32_t a;
    asm("{ .reg .u64 t; cvta.to.shared.u64 t, %1; cvt.u32.u64 %0, t; }" : "=r"(a) : "l"(p));
    return a;
}
__device__ __forceinline__ void cp16(uint32_t dst, const void* src) {
    asm volatile("cp.async.ca.shared.global [%0], [%1], 16;" :: "r"(dst), "l"(src) : "memory");
}
__device__ __forceinline__ void cp_commit() { asm volatile("cp.async.commit_group;" ::: "memory"); }
__device__ __forceinline__ void cp_wait1()  { asm volatile("cp.async.wait_group 1;" ::: "memory"); }
__device__ __forceinline__ void cp_wait0()  { asm volatile("cp.async.wait_group 0;" ::: "memory"); }
__device__ __forceinline__ void ldm4(uint32_t* r, uint32_t addr) {
    asm volatile("ldmatrix.sync.aligned.m8n8.x4.shared.b16 {%0,%1,%2,%3}, [%4];"
        : "=r"(r[0]), "=r"(r[1]), "=r"(r[2]), "=r"(r[3]) : "r"(addr));
}
__device__ __forceinline__ void mma16816(float* d, const uint32_t* a, const uint32_t* b) {
    asm volatile("mma.sync.aligned.m16n8k16.row.col.f32.f16.f16.f32 "
        "{%0,%1,%2,%3}, {%4,%5,%6,%7}, {%8,%9}, {%0,%1,%2,%3};"
        : "+f"(d[0]), "+f"(d[1]), "+f"(d[2]), "+f"(d[3])
        : "r"(a[0]), "r"(a[1]), "r"(a[2]), "r"(a[3]), "r"(b[0]), "r"(b[1]));
}

// ---------------- K1: build B = W^T (fp16) + self-row gather, merged ----------------
// blocks [0, 2304): weight repack; blocks [2304, 2816): self gather (4 rows each)
__global__ void prep_kernel(const float* __restrict__ weight,
                            const float* __restrict__ relw,
                            const float* __restrict__ emb,
                            const int* __restrict__ nodes) {
    int blk = blockIdx.x;
    int t = threadIdx.x;
    if (blk < 2304) {
        int j = blk >> 8;        // 0..8
        int n = blk & 255;
        int k = j * 256 + t;
        float v;
        if (k < NR * ND) {
            int r = k >> 8, d = k & 255;
            v = relw[((size_t)r * ND + n) * ND + d];
        } else {
            v = weight[n * ND + (k - NR * ND)];
        }
        g_Bh[(size_t)n * KTOT + k] = __float2half_rn(v);
    } else {
        int w = blk - 2304;
        int b = w * 4 + (t >> 6);
        int c = t & 63;
        int src = nodes[b];
        float4 v = ((const float4*)emb)[(size_t)src * 64 + c];
        size_t base = (size_t)b * KTOT + NR * ND + c * 4;
        __half2* dst = (__half2*)&g_Ah[base];
        dst[0] = __floats2half2_rn(v.x, v.y);
        dst[1] = __floats2half2_rn(v.z, v.w);
    }
}

// ---------------- K2: mask scan (ballot x2 rounds) -> index list -> MLP=4 gather ----------------
#define LIST_CAP 512
__global__ __launch_bounds__(256, 8) void mask_agg_kernel(const float* __restrict__ masks,
                                                          const float* __restrict__ emb,
                                                          const int* __restrict__ unique_idx) {
    __shared__ uint32_t s_bits[256];
    __shared__ uint16_t s_list[LIST_CAP];
    __shared__ int s_wtot[8];
    int t = threadIdx.x;
    int lane = t & 31;
    int w = t >> 5;
    int rb = blockIdx.x;
    int r = rb >> 11;
    int b = rb & 2047;

    const float4* row = (const float4*)(masks + (size_t)rb * NU);
#pragma unroll
    for (int half = 0; half < 2; half++) {       // 2 rounds of 4 float4 (16 regs)
        float4 v[4];
#pragma unroll
        for (int q = 0; q < 4; q++) v[q] = __ldcs(&row[(half * 4 + q) * 256 + t]);
#pragma unroll
        for (int q = 0; q < 4; q++) {
            int c = half * 4 + q;
            uint32_t bx = __ballot_sync(0xffffffffu, v[q].x != 0.0f);
            uint32_t by = __ballot_sync(0xffffffffu, v[q].y != 0.0f);
            uint32_t bz = __ballot_sync(0xffffffffu, v[q].z != 0.0f);
            uint32_t bw = __ballot_sync(0xffffffffu, v[q].w != 0.0f);
            if (lane == 0) {
                int g = c * 8 + w;
                s_bits[g * 4 + 0] = bx;
                s_bits[g * 4 + 1] = by;
                s_bits[g * 4 + 2] = bz;
                s_bits[g * 4 + 3] = bw;
            }
        }
    }
    __syncthreads();

    int Wd = w * 32 + lane;
    uint32_t bits = s_bits[Wd];
    int c = __popc(bits);
    int pre = c;
#pragma unroll
    for (int o = 1; o < 32; o <<= 1) {
        int x = __shfl_up_sync(0xffffffffu, pre, o);
        if (lane >= o) pre += x;
    }
    if (lane == 31) s_wtot[w] = pre;
    int excl = pre - c;
    __syncthreads();

    int base = 0, cnt = 0;
#pragma unroll
    for (int i = 0; i < 8; i++) {
        int x = s_wtot[i];
        if (i < w) base += x;
        cnt += x;
    }
    int pos = base + excl;
    {
        uint32_t bb = bits;
        int comp = Wd & 3;
        int g = Wd >> 2;
        int f4base = (g >> 3) * 256 + (g & 7) * 32;
        while (bb) {
            int j = __ffs(bb) - 1;
            bb &= bb - 1;
            if (pos < LIST_CAP) s_list[pos] = (uint16_t)((f4base + j) * 4 + comp);
            pos++;
        }
    }
    __syncthreads();

    int n = cnt < LIST_CAP ? cnt : LIST_CAP;
    float acc = 0.0f;
    int i = 0;
    for (; i + 4 <= n; i += 4) {
        int u0 = s_list[i], u1 = s_list[i + 1], u2 = s_list[i + 2], u3 = s_list[i + 3];
        int n0 = __ldg(&unique_idx[u0]);
        int n1 = __ldg(&unique_idx[u1]);
        int n2 = __ldg(&unique_idx[u2]);
        int n3 = __ldg(&unique_idx[u3]);
        float v0 = emb[(size_t)n0 * ND + t];
        float v1 = emb[(size_t)n1 * ND + t];
        float v2 = emb[(size_t)n2 * ND + t];
        float v3 = emb[(size_t)n3 * ND + t];
        acc = (((acc + v0) + v1) + v2) + v3;
    }
    for (; i < n; i++) acc += emb[(size_t)__ldg(&unique_idx[s_list[i]]) * ND + t];

    float val = acc * (1.0f / ((float)cnt + 1e-10f));
    g_Ah[(size_t)b * KTOT + r * ND + t] = __float2half_rn(val);
}

// ---------------- K3: mma.sync fp16 GEMM, 128x64 tile ----------------
// 8 warps (2m x 4n), warp tile 64x16, k-chunk 32, cp.async double-buffered.
// grid (16, 4, GSPLIT) = 576 blocks. SMEM/buf: A 10240 + B 5120 = 15360.
#define SM_AH 0
#define SM_BH 10240
#define SM_BUF 15360
#define GSMEM (2 * SM_BUF)

__device__ __forceinline__ void load_chunk(uint32_t sbuf, int m0, int n0, int kc, int tid) {
#pragma unroll
    for (int p = 0; p < 2; p++) {
        int o = tid + p * 256;
        int row = o >> 2;
        int c16 = o & 3;
        const __half* g = g_Ah + (size_t)(m0 + row) * KTOT + kc + c16 * 8;
        cp16(sbuf + SM_AH + row * 80 + c16 * 16, g);
    }
    {
        int row = tid >> 2;
        int c16 = tid & 3;
        const __half* g = g_Bh + (size_t)(n0 + row) * KTOT + kc + c16 * 8;
        cp16(sbuf + SM_BH + row * 80 + c16 * 16, g);
    }
}

__global__ __launch_bounds__(256, 4) void gemm_mma_kernel() {
    extern __shared__ char smem[];
    uint32_t sb = smem_u32(smem);
    int tid = threadIdx.x;
    int lane = tid & 31;
    int wid = tid >> 5;
    int wm = wid >> 2;          // 0..1
    int wn = wid & 3;           // 0..3 (16 n each)
    int m0 = blockIdx.x * 128;
    int n0 = blockIdx.y * 64;
    int sp = blockIdx.z;
    int kb = sp * GKSPL;

    float acc[4][2][4];
#pragma unroll
    for (int mi = 0; mi < 4; mi++)
#pragma unroll
        for (int nj = 0; nj < 2; nj++)
#pragma unroll
            for (int q = 0; q < 4; q++) acc[mi][nj][q] = 0.0f;

    load_chunk(sb, m0, n0, kb, tid);
    cp_commit();

    int lr = lane & 15;
    int lch = (lane >> 4) * 8;

    for (int it = 0; it < GITERS; it++) {
        uint32_t cbuf = sb + (it & 1) * SM_BUF;
        if (it + 1 < GITERS) {
            load_chunk(sb + ((it + 1) & 1) * SM_BUF, m0, n0, kb + (it + 1) * GCHUNK, tid);
            cp_commit();
            cp_wait1();
        } else {
            cp_wait0();
        }
        __syncthreads();

#pragma unroll
        for (int s = 0; s < 2; s++) {
            uint32_t ah[4][4], bh[2][2];
#pragma unroll
            for (int mi = 0; mi < 4; mi++) {
                uint32_t off = (uint32_t)(wm * 64 + mi * 16 + lr) * 80 + (s * 16 + lch) * 2;
                ldm4(ah[mi], cbuf + SM_AH + off);
            }
            {
                uint32_t off = (uint32_t)(wn * 16 + lr) * 80 + (s * 16 + lch) * 2;
                uint32_t r[4];
                ldm4(r, cbuf + SM_BH + off);
                bh[0][0] = r[0]; bh[0][1] = r[2];
                bh[1][0] = r[1]; bh[1][1] = r[3];
            }
#pragma unroll
            for (int mi = 0; mi < 4; mi++)
#pragma unroll
                for (int nj = 0; nj < 2; nj++)
                    mma16816(acc[mi][nj], ah[mi], bh[nj]);
        }
        __syncthreads();
    }

    float* pB = g_part + (size_t)sp * NB * ND;
    int g = lane >> 2;
    int tq = lane & 3;
#pragma unroll
    for (int mi = 0; mi < 4; mi++) {
#pragma unroll
        for (int nj = 0; nj < 2; nj++) {
            int m = m0 + wm * 64 + mi * 16 + g;
            int n = n0 + wn * 16 + nj * 8 + tq * 2;
            float2 v0 = {acc[mi][nj][0], acc[mi][nj][1]};
            float2 v1 = {acc[mi][nj][2], acc[mi][nj][3]};
            *(float2*)&pB[(size_t)m * ND + n] = v0;
            *(float2*)&pB[(size_t)(m + 8) * ND + n] = v1;
        }
    }
}

// ---------------- K4: deterministic reduce + ReLU ----------------
__global__ void reduce_relu_kernel(float* __restrict__ out) {
    int idx = blockIdx.x * 256 + threadIdx.x;
    const float4* p = (const float4*)g_part;
    float4 s = p[idx];
#pragma unroll
    for (int sp = 1; sp < GSPLIT; sp++) {
        float4 v = p[(size_t)sp * (NB * ND / 4) + idx];
        s.x += v.x; s.y += v.y; s.z += v.z; s.w += v.w;
    }
    s.x = s.x > 0.0f ? s.x : 0.0f;
    s.y = s.y > 0.0f ? s.y : 0.0f;
    s.z = s.z > 0.0f ? s.z : 0.0f;
    s.w = s.w > 0.0f ? s.w : 0.0f;
    ((float4*)out)[idx] = s;
}

// ---------------- launch (serial, single stream) ----------------
extern "C" void kernel_launch(void* const* d_in, const int* in_sizes, int n_in,
                              void* d_out, int out_size) {
    const int*   nodes  = nullptr;
    const int*   uniq   = nullptr;
    const float* masks  = nullptr;
    const float* emb    = nullptr;
    const float* weight = nullptr;
    const float* relw   = nullptr;

    for (int i = 0; i < n_in; i++) {
        switch (in_sizes[i]) {
            case NB:           nodes  = (const int*)d_in[i];   break;
            case NU:           uniq   = (const int*)d_in[i];   break;
            case NR * NB * NU: masks  = (const float*)d_in[i]; break;
            case 100000 * ND:  emb    = (const float*)d_in[i]; break;
            case ND * ND:      weight = (const float*)d_in[i]; break;
            case NR * ND * ND: relw   = (const float*)d_in[i]; break;
            default: break;
        }
    }
    float* out = (float*)d_out;

    static int smem_set = 0;
    if (!smem_set) {
        cudaFuncSetAttribute(gemm_mma_kernel, cudaFuncAttributeMaxDynamicSharedMemorySize, GSMEM);
        smem_set = 1;
    }

    prep_kernel<<<2304 + NB / 4, 256>>>(weight, relw, emb, nodes);
    mask_agg_kernel<<<NR * NB, 256>>>(masks, emb, uniq);
    dim3 g3(NB / 128, ND / 64, GSPLIT);
    gemm_mma_kernel<<<g3, 256, GSMEM>>>();
    reduce_relu_kernel<<<NB * ND / 4 / 256, 256>>>(out);
}